// round 10
// baseline (speedup 1.0000x reference)
#include <cuda_runtime.h>

// ---------------------------------------------------------------------------
// EnergySRB R10:
//  - finalize fused into main: species-cast prologue distributed over all
//    CTAs; energy outputs written by the last CTA (atomic-counter pattern),
//    which also re-zeros g_bins / counter so graph replays stay deterministic.
//  - grid sized for 152 SMs (GB300) * 2 CTAs.
//  - hot loop unchanged from R9 (CULL -17, smem bins, packed species, 8x
//    replicated coef table, clamped dvcut).
// ---------------------------------------------------------------------------

#define A2B_F 1.8897261258369282f
#define RC_F 9.826575854352027f          // 5.2 * A2B (bohr)
#define K1_F (A2B_F / RC_F)              // dv*K1 = d/rc
#define L2E_F 1.4426950408889634f
#define CULL_F (-17.0f)
#define DVCLAMP_F 5.19f                  // < 5.2 angstrom: guarantees u > 0

#define MAX_ATOKENS (512 * 1024)
#define MAX_MOLS (8192)
#define BIN_STRIDE 132                    // 528B stride -> spreads L2 slice hash
#define BLOCK 1024
#define TAB_WORDS 272                     // 8 replicas * 17 float2 = 1088B
#define NSM 152

__device__ unsigned int g_packed[MAX_ATOKENS / 16];   // 2-bit species codes
__device__ float g_bins[MAX_MOLS * BIN_STRIDE];
__device__ float2 g_tab[16];                          // (pre, dfac*A2B*L2E)
__device__ float g_dvcut;
__device__ unsigned int g_ctr;                        // last-CTA counter

__device__ __forceinline__ float rcp_approx(float x) {
    float y; asm("rcp.approx.f32 %0, %1;" : "=f"(y) : "f"(x)); return y;
}
__device__ __forceinline__ float ex2_approx(float x) {
    float y; asm("ex2.approx.f32 %0, %1;" : "=f"(y) : "f"(x)); return y;
}

// ---------------------------------------------------------------------------
__global__ void init_kernel(const int* __restrict__ species,
                            const float* __restrict__ pre_tab,
                            const float* __restrict__ dfac_tab,
                            int n_sp, int n_mol, int ne2,
                            int bin_stride, int do_pack) {
    int t = blockIdx.x * blockDim.x + threadIdx.x;
    if (do_pack) {
        int n4f = (n_sp >> 4) << 2;       // int4 groups forming full 16-atom words
        if (t < n4f) {
            int4 v = ((const int4*)species)[t];
            unsigned int chunk =
                ((unsigned)v.x & 3u)        | (((unsigned)v.y & 3u) << 2) |
                (((unsigned)v.z & 3u) << 4) | (((unsigned)v.w & 3u) << 6);
            unsigned int sub = (unsigned)t & 3u;
            unsigned int w = chunk << (sub * 8u);
            unsigned int gbase = (unsigned)(threadIdx.x & 31) & ~3u;
            unsigned int mask = 0xFu << gbase;
            w |= __shfl_xor_sync(mask, w, 1);
            w |= __shfl_xor_sync(mask, w, 2);
            if (sub == 0) g_packed[t >> 2] = w;
        }
        if (t == n4f && (n_sp & 15)) {    // partial last word
            int wi = n_sp >> 4;
            unsigned int w = 0;
            int base = wi << 4;
            for (int j = 0; j < 16; j++) {
                int a = base + j;
                unsigned int v = (a < n_sp) ? ((unsigned int)species[a] & 3u) : 0u;
                w |= v << (2 * j);
            }
            g_packed[wi] = w;
        }
        if (t < ne2 && t < 16)
            g_tab[t] = make_float2(pre_tab[t], dfac_tab[t] * A2B_F * L2E_F);
        if (t == 0) {
            float m = -1e30f;
            int n = (ne2 < 16) ? ne2 : 16;
            for (int k = 0; k < n; k++) {
                float c = dfac_tab[k] * A2B_F * L2E_F;
                if (c > m) m = c;
            }
            float cut = (m < 0.0f) ? (CULL_F / m) : 1e30f;
            if (cut > DVCLAMP_F) cut = DVCLAMP_F;   // survivors => u > 0
            g_dvcut = cut;
        }
    }
    if (t < n_mol) g_bins[t * bin_stride] = 0.0f;
}

// ---------------------------------------------------------------------------
// Main kernel, fused finalize. mode: 0=energy only, 1=[species|energy], 2=species.
// smem: [0..TAB_WORDS) coef table replicas | [.. +n_mol_pad) bins | packed.
// ---------------------------------------------------------------------------
__global__ void __launch_bounds__(BLOCK, 2)
srb_fused(const int* __restrict__ idx0, const int* __restrict__ idx1,
          const float* __restrict__ dist,
          const int* __restrict__ species, const float* __restrict__ energies,
          float* __restrict__ out,
          int nv, int na_shift, int bin_stride, int nwords,
          int n_mol, int n_mol_pad, int n_sp, int mode)
{
    extern __shared__ unsigned int s_mem[];
    float2* s_tab = (float2*)s_mem;                // 8 replicas, stride 17
    float* s_bins = (float*)(s_mem + TAB_WORDS);
    unsigned int* s_pk = s_mem + TAB_WORDS + n_mol_pad;
    __shared__ unsigned int s_last;

    if (threadIdx.x < 128) {
        int rep = threadIdx.x >> 4;
        int e = threadIdx.x & 15;
        s_tab[rep * 17 + e] = g_tab[e];
    }
    for (int j = threadIdx.x; j < n_mol; j += BLOCK)
        s_bins[j] = 0.0f;
    {
        const int4* __restrict__ src = (const int4*)g_packed;
        int4* dst = (int4*)s_pk;
        int nv4 = nwords >> 2;
        for (int j = threadIdx.x; j < nv4; j += BLOCK)
            dst[j] = src[j];
    }
    float dvcut = g_dvcut;
    int rbase = (threadIdx.x & 7) * 17;            // per-lane table replica

    int tid = blockIdx.x * BLOCK + threadIdx.x;
    int stride = gridDim.x * BLOCK;

    // Prologue: distributed species->float cast (bins-independent)
    if (mode == 1 || mode == 2) {
        int n4 = n_sp >> 2;
        for (int j = tid; j < n4; j += stride) {
            int4 s = ((const int4*)species)[j];
            ((float4*)out)[j] = make_float4((float)s.x, (float)s.y,
                                            (float)s.z, (float)s.w);
        }
        int rem = n_sp & 3;
        if (tid < rem) {
            int a = (n_sp & ~3) + tid;
            out[a] = (float)species[a];
        }
    }
    __syncthreads();

    const int4* __restrict__ p0 = (const int4*)idx0;
    const int4* __restrict__ p1 = (const int4*)idx1;
    const float4* __restrict__ pd = (const float4*)dist;

    for (int i = tid; i < nv; i += stride) {
        int4 a = __ldcs(p0 + i);
        int4 b = __ldcs(p1 + i);
        float4 dd = __ldcs(pd + i);

        int ia[4] = {a.x, a.y, a.z, a.w};
        int ib[4] = {b.x, b.y, b.z, b.w};
        float dv[4] = {dd.x, dd.y, dd.z, dd.w};

        #pragma unroll
        for (int j = 0; j < 4; j++) {
            float dvj = dv[j];
            if (dvj < dvcut) {                     // safe cull; implies u > 0
                int i0 = ia[j], i1 = ib[j];
                unsigned int w0 = s_pk[i0 >> 4];
                unsigned int w1 = s_pk[i1 >> 4];
                int s0 = (int)((w0 >> ((i0 & 15) << 1)) & 3u);
                int s1 = (int)((w1 >> ((i1 & 15) << 1)) & 3u);
                float2 c = s_tab[rbase + ((s0 << 2) | s1)];

                float t = dvj * K1_F;
                float u = fmaf(-t, t, 1.0f);       // 1 - (d/rc)^2, > 0 here
                float r = rcp_approx(u);
                float arg = fmaf(c.y, dvj, fmaf(-L2E_F, r, L2E_F));

                if (arg > CULL_F) {
                    float srb = c.x * ex2_approx(arg);
                    int mol = i0 >> na_shift;
                    atomicAdd(&s_bins[mol], srb);  // smem RED (spread banks)
                }
            }
        }
    }

    // flush per-CTA bins to global
    __syncthreads();
    for (int j = threadIdx.x; j < n_mol; j += BLOCK) {
        float v = s_bins[j];
        if (v != 0.0f)
            atomicAdd(&g_bins[j * bin_stride], v);
    }

    // last-CTA epilogue: write energies, clean device state for next replay
    __threadfence();
    __syncthreads();
    if (threadIdx.x == 0)
        s_last = atomicAdd(&g_ctr, 1u);
    __syncthreads();
    if (s_last == (unsigned)(gridDim.x - 1)) {
        if (mode != 2) {
            int base = (mode == 1) ? n_sp : 0;
            for (int j = threadIdx.x; j < n_mol; j += BLOCK) {
                out[base + j] = energies[j] + g_bins[j * bin_stride];
                g_bins[j * bin_stride] = 0.0f;     // re-zero for next call
            }
        } else {
            for (int j = threadIdx.x; j < n_mol; j += BLOCK)
                g_bins[j * bin_stride] = 0.0f;
        }
        __threadfence();
        if (threadIdx.x == 0)
            g_ctr = 0u;                            // reset counter
    }
}

// tail pairs [p_begin, P) scalar (exact, no cull)
__global__ void srb_tail(const int* __restrict__ idx0, const int* __restrict__ idx1,
                         const float* __restrict__ dist,
                         int p_begin, int P, int na_shift, int bin_stride)
{
    int p = p_begin + blockIdx.x * blockDim.x + threadIdx.x;
    if (p < P) {
        int i0 = idx0[p], i1 = idx1[p];
        float t = dist[p] * K1_F;
        float u = fmaf(-t, t, 1.0f);
        if (u > 0.0f) {
            unsigned int w0 = g_packed[i0 >> 4];
            unsigned int w1 = g_packed[i1 >> 4];
            int s0 = (int)((w0 >> ((i0 & 15) << 1)) & 3u);
            int s1 = (int)((w1 >> ((i1 & 15) << 1)) & 3u);
            float2 c = g_tab[(s0 << 2) + s1];
            float r = rcp_approx(u);
            float arg = fmaf(c.y, dist[p], fmaf(-L2E_F, r, L2E_F));
            float srb = c.x * ex2_approx(arg);
            int mol = i0 >> na_shift;
            atomicAdd(&g_bins[mol * bin_stride], srb);
        }
    }
}

// ---------------------------------------------------------------------------
// Non-fused main (used when a tail would race the fused epilogue)
// ---------------------------------------------------------------------------
__global__ void __launch_bounds__(BLOCK, 2)
srb_main_sbin(const int* __restrict__ idx0, const int* __restrict__ idx1,
              const float* __restrict__ dist,
              int nv, int na_shift, int bin_stride, int nwords,
              int n_mol, int n_mol_pad)
{
    extern __shared__ unsigned int s_mem[];
    float2* s_tab = (float2*)s_mem;
    float* s_bins = (float*)(s_mem + TAB_WORDS);
    unsigned int* s_pk = s_mem + TAB_WORDS + n_mol_pad;

    if (threadIdx.x < 128) {
        int rep = threadIdx.x >> 4;
        int e = threadIdx.x & 15;
        s_tab[rep * 17 + e] = g_tab[e];
    }
    for (int j = threadIdx.x; j < n_mol; j += BLOCK)
        s_bins[j] = 0.0f;
    {
        const int4* __restrict__ src = (const int4*)g_packed;
        int4* dst = (int4*)s_pk;
        int nv4 = nwords >> 2;
        for (int j = threadIdx.x; j < nv4; j += BLOCK)
            dst[j] = src[j];
    }
    float dvcut = g_dvcut;
    int rbase = (threadIdx.x & 7) * 17;
    __syncthreads();

    int tid = blockIdx.x * BLOCK + threadIdx.x;
    int stride = gridDim.x * BLOCK;

    const int4* __restrict__ p0 = (const int4*)idx0;
    const int4* __restrict__ p1 = (const int4*)idx1;
    const float4* __restrict__ pd = (const float4*)dist;

    for (int i = tid; i < nv; i += stride) {
        int4 a = __ldcs(p0 + i);
        int4 b = __ldcs(p1 + i);
        float4 dd = __ldcs(pd + i);

        int ia[4] = {a.x, a.y, a.z, a.w};
        int ib[4] = {b.x, b.y, b.z, b.w};
        float dv[4] = {dd.x, dd.y, dd.z, dd.w};

        #pragma unroll
        for (int j = 0; j < 4; j++) {
            float dvj = dv[j];
            if (dvj < dvcut) {
                int i0 = ia[j], i1 = ib[j];
                unsigned int w0 = s_pk[i0 >> 4];
                unsigned int w1 = s_pk[i1 >> 4];
                int s0 = (int)((w0 >> ((i0 & 15) << 1)) & 3u);
                int s1 = (int)((w1 >> ((i1 & 15) << 1)) & 3u);
                float2 c = s_tab[rbase + ((s0 << 2) | s1)];

                float t = dvj * K1_F;
                float u = fmaf(-t, t, 1.0f);
                float r = rcp_approx(u);
                float arg = fmaf(c.y, dvj, fmaf(-L2E_F, r, L2E_F));

                if (arg > CULL_F) {
                    float srb = c.x * ex2_approx(arg);
                    int mol = i0 >> na_shift;
                    atomicAdd(&s_bins[mol], srb);
                }
            }
        }
    }

    __syncthreads();
    for (int j = threadIdx.x; j < n_mol; j += BLOCK) {
        float v = s_bins[j];
        if (v != 0.0f)
            atomicAdd(&g_bins[j * bin_stride], v);
    }
}

// ---------------------------------------------------------------------------
// Generic fallback
// ---------------------------------------------------------------------------
__global__ void __launch_bounds__(256)
srb_kernel_generic(const int* __restrict__ idx0, const int* __restrict__ idx1,
                   const float* __restrict__ dist, const int* __restrict__ species,
                   const float* __restrict__ pre_tab, const float* __restrict__ dfac_tab,
                   int P, int n_elem, int na_shift, int n_atoms, int bin_stride)
{
    __shared__ float2 s_tab[64];
    int ne2 = n_elem * n_elem;
    for (int j = threadIdx.x; j < ne2; j += blockDim.x)
        s_tab[j] = make_float2(pre_tab[j], dfac_tab[j] * A2B_F * L2E_F);
    __syncthreads();

    int tid = blockIdx.x * blockDim.x + threadIdx.x;
    int stride = gridDim.x * blockDim.x;
    for (int p = tid; p < P; p += stride) {
        int i0 = idx0[p], i1 = idx1[p];
        float t = dist[p] * K1_F;
        float u = fmaf(-t, t, 1.0f);
        if (u > 0.0f) {
            int s0 = species[i0];
            int s1 = species[i1];
            float2 c = s_tab[s0 * n_elem + s1];
            float r = rcp_approx(u);
            float arg = fmaf(c.y, dist[p], fmaf(-L2E_F, r, L2E_F));
            float srb = c.x * ex2_approx(arg);
            int mol = (na_shift >= 0) ? (i0 >> na_shift) : (i0 / n_atoms);
            atomicAdd(&g_bins[mol * bin_stride], srb);
        }
    }
}

// ---------------------------------------------------------------------------
__global__ void finalize_kernel(const float* __restrict__ energies,
                                const int* __restrict__ species,
                                float* __restrict__ out,
                                int n_mol, int n_sp, int bin_stride, int mode) {
    int t = blockIdx.x * blockDim.x + threadIdx.x;
    if (mode == 1) {
        int n4 = n_sp >> 2;
        if (t < n4) {
            int4 s = ((const int4*)species)[t];
            float4 f = make_float4((float)s.x, (float)s.y, (float)s.z, (float)s.w);
            ((float4*)out)[t] = f;
        } else if (t < n4 + n_mol) {
            int m = t - n4;
            out[n_sp + m] = energies[m] + g_bins[m * bin_stride];
        }
        int rem = n_sp & 3;
        if (t < rem) {
            int a = (n_sp & ~3) + t;
            out[a] = (float)species[a];
        }
    } else if (mode == 2) {
        if (t < n_sp) out[t] = (float)species[t];
    } else {
        if (t < n_mol) out[t] = energies[t] + g_bins[t * bin_stride];
    }
}

// ---------------------------------------------------------------------------
extern "C" void kernel_launch(void* const* d_in, const int* in_sizes, int n_in,
                              void* d_out, int out_size) {
    const int*   species  = (const int*)d_in[0];
    const float* energies = (const float*)d_in[1];
    const int*   ai12     = (const int*)d_in[2];
    const float* dist     = (const float*)d_in[3];
    const float* pre_tab  = (const float*)d_in[4];
    const float* dfac_tab = (const float*)d_in[5];

    int n_sp  = in_sizes[0];
    int n_mol = in_sizes[1];
    int P     = in_sizes[3];
    int n_atoms = (n_mol > 0) ? (n_sp / n_mol) : 1;
    if (n_atoms < 1) n_atoms = 1;

    int n_elem = 1;
    while (n_elem * n_elem < in_sizes[4]) n_elem++;

    int na_shift = -1;
    if ((n_atoms & (n_atoms - 1)) == 0) {
        int s = 0; int v = n_atoms;
        while (v > 1) { v >>= 1; s++; }
        na_shift = s;
    }

    bool packed = (n_elem == 4) && (n_sp <= MAX_ATOKENS) && (na_shift >= 0);
    int bin_stride = (n_mol <= MAX_MOLS) ? BIN_STRIDE : 1;

    int nwords = (n_sp + 15) >> 4;
    int nwords_pad = (nwords + 3) & ~3;
    int n_mol_pad = (n_mol + 3) & ~3;

    float* out = (float*)d_out;
    int mode;
    if (out_size == n_mol) mode = 0;
    else if (out_size == n_sp + n_mol) mode = 1;
    else if (out_size == n_sp) mode = 2;
    else mode = 0;

    long long init_n = n_mol;
    if (packed) {
        long long pack_n = ((long long)(n_sp >> 4) << 2) + 1;
        if (pack_n > init_n) init_n = pack_n;
    }
    if (init_n < 16) init_n = 16;
    int init_grid = (int)((init_n + 255) / 256);
    init_kernel<<<init_grid, 256>>>(species, pre_tab, dfac_tab,
                                    n_sp, n_mol, n_elem * n_elem,
                                    bin_stride, packed ? 1 : 0);

    const int* idx0 = ai12;
    const int* idx1 = ai12 + P;

    size_t smem_sbin = (size_t)(TAB_WORDS + n_mol_pad + nwords_pad) * 4;
    bool sbin_fits = packed && (n_mol <= MAX_MOLS) && (2 * smem_sbin <= 220 * 1024);
    int rem = P & 3;

    if (sbin_fits && rem == 0) {
        // fully fused path (no tail to race the epilogue)
        (void)cudaFuncSetAttribute(srb_fused,
                                   cudaFuncAttributeMaxDynamicSharedMemorySize,
                                   (int)smem_sbin);
        int nv = P >> 2;
        int grid = NSM * 2;
        long long want = ((long long)nv + BLOCK - 1) / BLOCK;
        if (want < grid) grid = (int)(want > 0 ? want : 1);
        srb_fused<<<grid, BLOCK, smem_sbin>>>(idx0, idx1, dist,
                                              species, energies, out,
                                              nv, na_shift, bin_stride,
                                              nwords_pad, n_mol, n_mol_pad,
                                              n_sp, mode);
    } else if (sbin_fits) {
        (void)cudaFuncSetAttribute(srb_main_sbin,
                                   cudaFuncAttributeMaxDynamicSharedMemorySize,
                                   (int)smem_sbin);
        int nv = P >> 2;
        int grid = NSM * 2;
        long long want = ((long long)nv + BLOCK - 1) / BLOCK;
        if (want < grid) grid = (int)(want > 0 ? want : 1);
        if (grid < 1) grid = 1;
        srb_main_sbin<<<grid, BLOCK, smem_sbin>>>(idx0, idx1, dist,
                                                  nv, na_shift, bin_stride,
                                                  nwords_pad, n_mol, n_mol_pad);
        if (rem)
            srb_tail<<<1, 32>>>(idx0, idx1, dist, P - rem, P, na_shift, bin_stride);
        long long fin_threads = (mode == 1) ? ((long long)(n_sp >> 2) + n_mol + 4)
                              : ((mode == 2) ? n_sp : n_mol);
        int fin_grid = (int)((fin_threads + 255) / 256);
        if (fin_grid < 1) fin_grid = 1;
        finalize_kernel<<<fin_grid, 256>>>(energies, species, out,
                                           n_mol, n_sp, bin_stride, mode);
    } else {
        long long want = ((long long)P + 255) / 256;
        int grid = (want > 4736) ? 4736 : (int)(want > 0 ? want : 1);
        srb_kernel_generic<<<grid, 256>>>(idx0, idx1, dist, species,
                                          pre_tab, dfac_tab,
                                          P, n_elem, na_shift, n_atoms, bin_stride);
        long long fin_threads = (mode == 1) ? ((long long)(n_sp >> 2) + n_mol + 4)
                              : ((mode == 2) ? n_sp : n_mol);
        int fin_grid = (int)((fin_threads + 255) / 256);
        if (fin_grid < 1) fin_grid = 1;
        finalize_kernel<<<fin_grid, 256>>>(energies, species, out,
                                           n_mol, n_sp, bin_stride, mode);
    }
}

// round 11
// speedup vs baseline: 1.1862x; 1.1862x over previous
#include <cuda_runtime.h>

// ---------------------------------------------------------------------------
// EnergySRB R11 = R9 (best, 51.2us) + species-cast folded into init:
//  - init already loads each species int4 for 2-bit packing; reuse it to write
//    the float-cast output prologue. Finalize shrinks to n_mol energy writes.
//  - fused last-CTA epilogue from R10 REVERTED (serial tail + 304-grid 2nd
//    wave caused the regression). Grid back to 148*2=296.
//  - hot loop: CULL -17, clamped dvcut pre-cull, 2-bit packed species in smem,
//    8x-replicated coef table, smem bins + per-CTA REDG flush.
// ---------------------------------------------------------------------------

#define A2B_F 1.8897261258369282f
#define RC_F 9.826575854352027f          // 5.2 * A2B (bohr)
#define K1_F (A2B_F / RC_F)              // dv*K1 = d/rc
#define L2E_F 1.4426950408889634f
#define CULL_F (-17.0f)
#define DVCLAMP_F 5.19f                  // < 5.2 angstrom: guarantees u > 0

#define MAX_ATOKENS (512 * 1024)
#define MAX_MOLS (8192)
#define BIN_STRIDE 132                    // 528B stride -> spreads L2 slice hash
#define BLOCK 1024
#define TAB_WORDS 272                     // 8 replicas * 17 float2 = 1088B

__device__ unsigned int g_packed[MAX_ATOKENS / 16];   // 2-bit species codes
__device__ float g_bins[MAX_MOLS * BIN_STRIDE];
__device__ float2 g_tab[16];                          // (pre, dfac*A2B*L2E)
__device__ float g_dvcut;

__device__ __forceinline__ float rcp_approx(float x) {
    float y; asm("rcp.approx.f32 %0, %1;" : "=f"(y) : "f"(x)); return y;
}
__device__ __forceinline__ float ex2_approx(float x) {
    float y; asm("ex2.approx.f32 %0, %1;" : "=f"(y) : "f"(x)); return y;
}

// ---------------------------------------------------------------------------
// Init: pack species to 2 bits (shuffle combine), optional float cast of
// species into out[0..n_sp) (reuses the SAME int4 load), table, zero bins.
// ---------------------------------------------------------------------------
__global__ void init_kernel(const int* __restrict__ species,
                            const float* __restrict__ pre_tab,
                            const float* __restrict__ dfac_tab,
                            float* __restrict__ out_sp,
                            int n_sp, int n_mol, int ne2,
                            int bin_stride, int do_pack, int do_cast) {
    int t = blockIdx.x * blockDim.x + threadIdx.x;
    if (do_pack) {
        int n4 = n_sp >> 2;
        int n4f = (n_sp >> 4) << 2;       // int4 groups forming full 16-atom words
        if (t < n4) {
            int4 v = ((const int4*)species)[t];
            if (do_cast) {
                ((float4*)out_sp)[t] = make_float4((float)v.x, (float)v.y,
                                                   (float)v.z, (float)v.w);
            }
            if (t < n4f) {
                unsigned int chunk =
                    ((unsigned)v.x & 3u)        | (((unsigned)v.y & 3u) << 2) |
                    (((unsigned)v.z & 3u) << 4) | (((unsigned)v.w & 3u) << 6);
                unsigned int sub = (unsigned)t & 3u;
                unsigned int w = chunk << (sub * 8u);
                unsigned int gbase = (unsigned)(threadIdx.x & 31) & ~3u;
                unsigned int mask = 0xFu << gbase;
                w |= __shfl_xor_sync(mask, w, 1);
                w |= __shfl_xor_sync(mask, w, 2);
                if (sub == 0) g_packed[t >> 2] = w;
            }
        }
        if (t == n4 && (n_sp & 15)) {     // partial last packed word
            int wi = n_sp >> 4;
            unsigned int w = 0;
            int base = wi << 4;
            for (int j = 0; j < 16; j++) {
                int a = base + j;
                unsigned int v = (a < n_sp) ? ((unsigned int)species[a] & 3u) : 0u;
                w |= v << (2 * j);
            }
            g_packed[wi] = w;
        }
        if (do_cast && t < (n_sp & 3)) {  // cast remainder
            int a = (n_sp & ~3) + t;
            out_sp[a] = (float)species[a];
        }
        if (t < ne2 && t < 16)
            g_tab[t] = make_float2(pre_tab[t], dfac_tab[t] * A2B_F * L2E_F);
        if (t == 0) {
            float m = -1e30f;
            int n = (ne2 < 16) ? ne2 : 16;
            for (int k = 0; k < n; k++) {
                float c = dfac_tab[k] * A2B_F * L2E_F;
                if (c > m) m = c;
            }
            float cut = (m < 0.0f) ? (CULL_F / m) : 1e30f;
            if (cut > DVCLAMP_F) cut = DVCLAMP_F;   // survivors => u > 0
            g_dvcut = cut;
        }
    }
    if (t < n_mol) g_bins[t * bin_stride] = 0.0f;
}

// ---------------------------------------------------------------------------
// Main kernel (R9-proven). smem: coef table replicas | bins | packed species.
// ---------------------------------------------------------------------------
__global__ void __launch_bounds__(BLOCK, 2)
srb_main_sbin(const int* __restrict__ idx0, const int* __restrict__ idx1,
              const float* __restrict__ dist,
              int nv, int na_shift, int bin_stride, int nwords,
              int n_mol, int n_mol_pad)
{
    extern __shared__ unsigned int s_mem[];
    float2* s_tab = (float2*)s_mem;                // 8 replicas, stride 17
    float* s_bins = (float*)(s_mem + TAB_WORDS);
    unsigned int* s_pk = s_mem + TAB_WORDS + n_mol_pad;

    if (threadIdx.x < 128) {
        int rep = threadIdx.x >> 4;
        int e = threadIdx.x & 15;
        s_tab[rep * 17 + e] = g_tab[e];
    }
    for (int j = threadIdx.x; j < n_mol; j += BLOCK)
        s_bins[j] = 0.0f;
    {
        const int4* __restrict__ src = (const int4*)g_packed;
        int4* dst = (int4*)s_pk;
        int nv4 = nwords >> 2;
        for (int j = threadIdx.x; j < nv4; j += BLOCK)
            dst[j] = src[j];
    }
    float dvcut = g_dvcut;
    int rbase = (threadIdx.x & 7) * 17;            // per-lane table replica
    __syncthreads();

    int tid = blockIdx.x * BLOCK + threadIdx.x;
    int stride = gridDim.x * BLOCK;

    const int4* __restrict__ p0 = (const int4*)idx0;
    const int4* __restrict__ p1 = (const int4*)idx1;
    const float4* __restrict__ pd = (const float4*)dist;

    for (int i = tid; i < nv; i += stride) {
        int4 a = __ldcs(p0 + i);
        int4 b = __ldcs(p1 + i);
        float4 dd = __ldcs(pd + i);

        int ia[4] = {a.x, a.y, a.z, a.w};
        int ib[4] = {b.x, b.y, b.z, b.w};
        float dv[4] = {dd.x, dd.y, dd.z, dd.w};

        #pragma unroll
        for (int j = 0; j < 4; j++) {
            float dvj = dv[j];
            if (dvj < dvcut) {                     // safe cull; implies u > 0
                int i0 = ia[j], i1 = ib[j];
                unsigned int w0 = s_pk[i0 >> 4];
                unsigned int w1 = s_pk[i1 >> 4];
                int s0 = (int)((w0 >> ((i0 & 15) << 1)) & 3u);
                int s1 = (int)((w1 >> ((i1 & 15) << 1)) & 3u);
                float2 c = s_tab[rbase + ((s0 << 2) | s1)];

                float t = dvj * K1_F;
                float u = fmaf(-t, t, 1.0f);       // 1 - (d/rc)^2, > 0 here
                float r = rcp_approx(u);
                float arg = fmaf(c.y, dvj, fmaf(-L2E_F, r, L2E_F));

                if (arg > CULL_F) {
                    float srb = c.x * ex2_approx(arg);
                    int mol = i0 >> na_shift;
                    atomicAdd(&s_bins[mol], srb);  // smem RED (spread banks)
                }
            }
        }
    }

    // flush per-CTA bins to global (coalesced lanes, distinct L2 sectors)
    __syncthreads();
    for (int j = threadIdx.x; j < n_mol; j += BLOCK) {
        float v = s_bins[j];
        if (v != 0.0f)
            atomicAdd(&g_bins[j * bin_stride], v);
    }
}

// tail pairs [p_begin, P) scalar (exact, no cull)
__global__ void srb_tail(const int* __restrict__ idx0, const int* __restrict__ idx1,
                         const float* __restrict__ dist,
                         int p_begin, int P, int na_shift, int bin_stride)
{
    int p = p_begin + blockIdx.x * blockDim.x + threadIdx.x;
    if (p < P) {
        int i0 = idx0[p], i1 = idx1[p];
        float t = dist[p] * K1_F;
        float u = fmaf(-t, t, 1.0f);
        if (u > 0.0f) {
            unsigned int w0 = g_packed[i0 >> 4];
            unsigned int w1 = g_packed[i1 >> 4];
            int s0 = (int)((w0 >> ((i0 & 15) << 1)) & 3u);
            int s1 = (int)((w1 >> ((i1 & 15) << 1)) & 3u);
            float2 c = g_tab[(s0 << 2) + s1];
            float r = rcp_approx(u);
            float arg = fmaf(c.y, dist[p], fmaf(-L2E_F, r, L2E_F));
            float srb = c.x * ex2_approx(arg);
            int mol = i0 >> na_shift;
            atomicAdd(&g_bins[mol * bin_stride], srb);
        }
    }
}

// ---------------------------------------------------------------------------
// Generic fallback (any n_elem / non-pow2 n_atoms / large n_sp)
// ---------------------------------------------------------------------------
__global__ void __launch_bounds__(256)
srb_kernel_generic(const int* __restrict__ idx0, const int* __restrict__ idx1,
                   const float* __restrict__ dist, const int* __restrict__ species,
                   const float* __restrict__ pre_tab, const float* __restrict__ dfac_tab,
                   int P, int n_elem, int na_shift, int n_atoms, int bin_stride)
{
    __shared__ float2 s_tab[64];
    int ne2 = n_elem * n_elem;
    for (int j = threadIdx.x; j < ne2; j += blockDim.x)
        s_tab[j] = make_float2(pre_tab[j], dfac_tab[j] * A2B_F * L2E_F);
    __syncthreads();

    int tid = blockIdx.x * blockDim.x + threadIdx.x;
    int stride = gridDim.x * blockDim.x;
    for (int p = tid; p < P; p += stride) {
        int i0 = idx0[p], i1 = idx1[p];
        float t = dist[p] * K1_F;
        float u = fmaf(-t, t, 1.0f);
        if (u > 0.0f) {
            int s0 = species[i0];
            int s1 = species[i1];
            float2 c = s_tab[s0 * n_elem + s1];
            float r = rcp_approx(u);
            float arg = fmaf(c.y, dist[p], fmaf(-L2E_F, r, L2E_F));
            float srb = c.x * ex2_approx(arg);
            int mol = (na_shift >= 0) ? (i0 >> na_shift) : (i0 / n_atoms);
            atomicAdd(&g_bins[mol * bin_stride], srb);
        }
    }
}

// ---------------------------------------------------------------------------
// Finalize. cast_done=1: species cast already written by init; only energies.
// ---------------------------------------------------------------------------
__global__ void finalize_kernel(const float* __restrict__ energies,
                                const int* __restrict__ species,
                                float* __restrict__ out,
                                int n_mol, int n_sp, int bin_stride,
                                int mode, int cast_done) {
    int t = blockIdx.x * blockDim.x + threadIdx.x;
    if (cast_done) {
        if (mode != 2) {
            int base = (mode == 1) ? n_sp : 0;
            if (t < n_mol)
                out[base + t] = energies[t] + g_bins[t * bin_stride];
        }
        return;
    }
    if (mode == 1) {
        int n4 = n_sp >> 2;
        if (t < n4) {
            int4 s = ((const int4*)species)[t];
            ((float4*)out)[t] = make_float4((float)s.x, (float)s.y,
                                            (float)s.z, (float)s.w);
        } else if (t < n4 + n_mol) {
            int m = t - n4;
            out[n_sp + m] = energies[m] + g_bins[m * bin_stride];
        }
        int rem = n_sp & 3;
        if (t < rem) {
            int a = (n_sp & ~3) + t;
            out[a] = (float)species[a];
        }
    } else if (mode == 2) {
        if (t < n_sp) out[t] = (float)species[t];
    } else {
        if (t < n_mol) out[t] = energies[t] + g_bins[t * bin_stride];
    }
}

// ---------------------------------------------------------------------------
extern "C" void kernel_launch(void* const* d_in, const int* in_sizes, int n_in,
                              void* d_out, int out_size) {
    const int*   species  = (const int*)d_in[0];
    const float* energies = (const float*)d_in[1];
    const int*   ai12     = (const int*)d_in[2];
    const float* dist     = (const float*)d_in[3];
    const float* pre_tab  = (const float*)d_in[4];
    const float* dfac_tab = (const float*)d_in[5];

    int n_sp  = in_sizes[0];
    int n_mol = in_sizes[1];
    int P     = in_sizes[3];
    int n_atoms = (n_mol > 0) ? (n_sp / n_mol) : 1;
    if (n_atoms < 1) n_atoms = 1;

    int n_elem = 1;
    while (n_elem * n_elem < in_sizes[4]) n_elem++;

    int na_shift = -1;
    if ((n_atoms & (n_atoms - 1)) == 0) {
        int s = 0; int v = n_atoms;
        while (v > 1) { v >>= 1; s++; }
        na_shift = s;
    }

    bool packed = (n_elem == 4) && (n_sp <= MAX_ATOKENS) && (na_shift >= 0);
    int bin_stride = (n_mol <= MAX_MOLS) ? BIN_STRIDE : 1;

    int nwords = (n_sp + 15) >> 4;
    int nwords_pad = (nwords + 3) & ~3;
    int n_mol_pad = (n_mol + 3) & ~3;

    float* out = (float*)d_out;
    int mode;
    if (out_size == n_mol) mode = 0;
    else if (out_size == n_sp + n_mol) mode = 1;
    else if (out_size == n_sp) mode = 2;
    else mode = 0;

    int do_cast = (packed && (mode == 1 || mode == 2)) ? 1 : 0;

    long long init_n = n_mol;
    if (packed) {
        long long pack_n = (long long)(n_sp >> 2) + 1;
        if (pack_n > init_n) init_n = pack_n;
    }
    if (init_n < 16) init_n = 16;
    int init_grid = (int)((init_n + 255) / 256);
    init_kernel<<<init_grid, 256>>>(species, pre_tab, dfac_tab, out,
                                    n_sp, n_mol, n_elem * n_elem,
                                    bin_stride, packed ? 1 : 0, do_cast);

    const int* idx0 = ai12;
    const int* idx1 = ai12 + P;

    size_t smem_sbin = (size_t)(TAB_WORDS + n_mol_pad + nwords_pad) * 4;
    bool sbin_fits = packed && (n_mol <= MAX_MOLS) && (2 * smem_sbin <= 220 * 1024);

    if (sbin_fits) {
        (void)cudaFuncSetAttribute(srb_main_sbin,
                                   cudaFuncAttributeMaxDynamicSharedMemorySize,
                                   (int)smem_sbin);
        int nv = P >> 2;
        int grid = 148 * 2;              // R9-proven
        long long want = ((long long)nv + BLOCK - 1) / BLOCK;
        if (want < grid) grid = (int)(want > 0 ? want : 1);
        if (grid < 1) grid = 1;
        srb_main_sbin<<<grid, BLOCK, smem_sbin>>>(idx0, idx1, dist,
                                                  nv, na_shift, bin_stride,
                                                  nwords_pad, n_mol, n_mol_pad);
        int rem = P & 3;
        if (rem)
            srb_tail<<<1, 32>>>(idx0, idx1, dist, P - rem, P, na_shift, bin_stride);

        long long fin_threads = do_cast ? n_mol
                              : ((mode == 1) ? ((long long)(n_sp >> 2) + n_mol + 4)
                              : ((mode == 2) ? n_sp : n_mol));
        int fin_grid = (int)((fin_threads + 255) / 256);
        if (fin_grid < 1) fin_grid = 1;
        finalize_kernel<<<fin_grid, 256>>>(energies, species, out,
                                           n_mol, n_sp, bin_stride, mode, do_cast);
    } else {
        long long want = ((long long)P + 255) / 256;
        int grid = (want > 4736) ? 4736 : (int)(want > 0 ? want : 1);
        srb_kernel_generic<<<grid, 256>>>(idx0, idx1, dist, species,
                                          pre_tab, dfac_tab,
                                          P, n_elem, na_shift, n_atoms, bin_stride);
        long long fin_threads = (mode == 1) ? ((long long)(n_sp >> 2) + n_mol + 4)
                              : ((mode == 2) ? n_sp : n_mol);
        int fin_grid = (int)((fin_threads + 255) / 256);
        if (fin_grid < 1) fin_grid = 1;
        finalize_kernel<<<fin_grid, 256>>>(energies, species, out,
                                           n_mol, n_sp, bin_stride, mode, 0);
    }
}

// round 12
// speedup vs baseline: 1.2045x; 1.0154x over previous
#include <cuda_runtime.h>

// ---------------------------------------------------------------------------
// EnergySRB R12 = R11 with the init serial-chain bug fixed:
//  - g_dvcut was computed by thread 0 via 16 DEPENDENT global loads (~5us of
//    single-thread latency). Now: lanes 0-15 of block 0 reuse their table
//    loads and do a 4-step shfl-xor max reduction; lane 0 writes g_dvcut.
//  - everything else identical to R11 (best: 50.7us): CULL -17, clamped-dvcut
//    pre-cull, 2-bit packed species in smem, 8x-replicated coef table, smem
//    bins + per-CTA REDG flush, species-cast folded into init, grid 296.
// ---------------------------------------------------------------------------

#define A2B_F 1.8897261258369282f
#define RC_F 9.826575854352027f          // 5.2 * A2B (bohr)
#define K1_F (A2B_F / RC_F)              // dv*K1 = d/rc
#define L2E_F 1.4426950408889634f
#define CULL_F (-17.0f)
#define DVCLAMP_F 5.19f                  // < 5.2 angstrom: guarantees u > 0

#define MAX_ATOKENS (512 * 1024)
#define MAX_MOLS (8192)
#define BIN_STRIDE 132                    // 528B stride -> spreads L2 slice hash
#define BLOCK 1024
#define TAB_WORDS 272                     // 8 replicas * 17 float2 = 1088B

__device__ unsigned int g_packed[MAX_ATOKENS / 16];   // 2-bit species codes
__device__ float g_bins[MAX_MOLS * BIN_STRIDE];
__device__ float2 g_tab[16];                          // (pre, dfac*A2B*L2E)
__device__ float g_dvcut;

__device__ __forceinline__ float rcp_approx(float x) {
    float y; asm("rcp.approx.f32 %0, %1;" : "=f"(y) : "f"(x)); return y;
}
__device__ __forceinline__ float ex2_approx(float x) {
    float y; asm("ex2.approx.f32 %0, %1;" : "=f"(y) : "f"(x)); return y;
}

// ---------------------------------------------------------------------------
// Init: pack species to 2 bits (shuffle combine), optional float cast of
// species into out[0..n_sp) (reuses the SAME int4 load), table + dvcut via
// warp reduction, zero bins.
// ---------------------------------------------------------------------------
__global__ void init_kernel(const int* __restrict__ species,
                            const float* __restrict__ pre_tab,
                            const float* __restrict__ dfac_tab,
                            float* __restrict__ out_sp,
                            int n_sp, int n_mol, int ne2,
                            int bin_stride, int do_pack, int do_cast) {
    int t = blockIdx.x * blockDim.x + threadIdx.x;
    if (do_pack) {
        int n4 = n_sp >> 2;
        int n4f = (n_sp >> 4) << 2;       // int4 groups forming full 16-atom words
        if (t < n4) {
            int4 v = ((const int4*)species)[t];
            if (do_cast) {
                ((float4*)out_sp)[t] = make_float4((float)v.x, (float)v.y,
                                                   (float)v.z, (float)v.w);
            }
            if (t < n4f) {
                unsigned int chunk =
                    ((unsigned)v.x & 3u)        | (((unsigned)v.y & 3u) << 2) |
                    (((unsigned)v.z & 3u) << 4) | (((unsigned)v.w & 3u) << 6);
                unsigned int sub = (unsigned)t & 3u;
                unsigned int w = chunk << (sub * 8u);
                unsigned int gbase = (unsigned)(threadIdx.x & 31) & ~3u;
                unsigned int mask = 0xFu << gbase;
                w |= __shfl_xor_sync(mask, w, 1);
                w |= __shfl_xor_sync(mask, w, 2);
                if (sub == 0) g_packed[t >> 2] = w;
            }
        }
        if (t == n4 && (n_sp & 15)) {     // partial last packed word
            int wi = n_sp >> 4;
            unsigned int w = 0;
            int base = wi << 4;
            for (int j = 0; j < 16; j++) {
                int a = base + j;
                unsigned int v = (a < n_sp) ? ((unsigned int)species[a] & 3u) : 0u;
                w |= v << (2 * j);
            }
            g_packed[wi] = w;
        }
        if (do_cast && t < (n_sp & 3)) {  // cast remainder
            int a = (n_sp & ~3) + t;
            out_sp[a] = (float)species[a];
        }
        // table + dvcut: lanes 0-15 of block 0, parallel loads + shfl reduce
        if (blockIdx.x == 0 && threadIdx.x < 16) {
            int lane = threadIdx.x;
            float c = -1e30f;
            if (lane < ne2) {
                float d = dfac_tab[lane] * A2B_F * L2E_F;
                g_tab[lane] = make_float2(pre_tab[lane], d);
                c = d;
            }
            #pragma unroll
            for (int off = 8; off; off >>= 1)
                c = fmaxf(c, __shfl_xor_sync(0xFFFFu, c, off));
            if (lane == 0) {
                float cut = (c < 0.0f) ? (CULL_F / c) : 1e30f;
                if (cut > DVCLAMP_F) cut = DVCLAMP_F;   // survivors => u > 0
                g_dvcut = cut;
            }
        }
    }
    if (t < n_mol) g_bins[t * bin_stride] = 0.0f;
}

// ---------------------------------------------------------------------------
// Main kernel (R9-proven). smem: coef table replicas | bins | packed species.
// ---------------------------------------------------------------------------
__global__ void __launch_bounds__(BLOCK, 2)
srb_main_sbin(const int* __restrict__ idx0, const int* __restrict__ idx1,
              const float* __restrict__ dist,
              int nv, int na_shift, int bin_stride, int nwords,
              int n_mol, int n_mol_pad)
{
    extern __shared__ unsigned int s_mem[];
    float2* s_tab = (float2*)s_mem;                // 8 replicas, stride 17
    float* s_bins = (float*)(s_mem + TAB_WORDS);
    unsigned int* s_pk = s_mem + TAB_WORDS + n_mol_pad;

    if (threadIdx.x < 128) {
        int rep = threadIdx.x >> 4;
        int e = threadIdx.x & 15;
        s_tab[rep * 17 + e] = g_tab[e];
    }
    for (int j = threadIdx.x; j < n_mol; j += BLOCK)
        s_bins[j] = 0.0f;
    {
        const int4* __restrict__ src = (const int4*)g_packed;
        int4* dst = (int4*)s_pk;
        int nv4 = nwords >> 2;
        for (int j = threadIdx.x; j < nv4; j += BLOCK)
            dst[j] = src[j];
    }
    float dvcut = g_dvcut;
    int rbase = (threadIdx.x & 7) * 17;            // per-lane table replica
    __syncthreads();

    int tid = blockIdx.x * BLOCK + threadIdx.x;
    int stride = gridDim.x * BLOCK;

    const int4* __restrict__ p0 = (const int4*)idx0;
    const int4* __restrict__ p1 = (const int4*)idx1;
    const float4* __restrict__ pd = (const float4*)dist;

    for (int i = tid; i < nv; i += stride) {
        int4 a = __ldcs(p0 + i);
        int4 b = __ldcs(p1 + i);
        float4 dd = __ldcs(pd + i);

        int ia[4] = {a.x, a.y, a.z, a.w};
        int ib[4] = {b.x, b.y, b.z, b.w};
        float dv[4] = {dd.x, dd.y, dd.z, dd.w};

        #pragma unroll
        for (int j = 0; j < 4; j++) {
            float dvj = dv[j];
            if (dvj < dvcut) {                     // safe cull; implies u > 0
                int i0 = ia[j], i1 = ib[j];
                unsigned int w0 = s_pk[i0 >> 4];
                unsigned int w1 = s_pk[i1 >> 4];
                int s0 = (int)((w0 >> ((i0 & 15) << 1)) & 3u);
                int s1 = (int)((w1 >> ((i1 & 15) << 1)) & 3u);
                float2 c = s_tab[rbase + ((s0 << 2) | s1)];

                float t = dvj * K1_F;
                float u = fmaf(-t, t, 1.0f);       // 1 - (d/rc)^2, > 0 here
                float r = rcp_approx(u);
                float arg = fmaf(c.y, dvj, fmaf(-L2E_F, r, L2E_F));

                if (arg > CULL_F) {
                    float srb = c.x * ex2_approx(arg);
                    int mol = i0 >> na_shift;
                    atomicAdd(&s_bins[mol], srb);  // smem RED (spread banks)
                }
            }
        }
    }

    // flush per-CTA bins to global (coalesced lanes, distinct L2 sectors)
    __syncthreads();
    for (int j = threadIdx.x; j < n_mol; j += BLOCK) {
        float v = s_bins[j];
        if (v != 0.0f)
            atomicAdd(&g_bins[j * bin_stride], v);
    }
}

// tail pairs [p_begin, P) scalar (exact, no cull)
__global__ void srb_tail(const int* __restrict__ idx0, const int* __restrict__ idx1,
                         const float* __restrict__ dist,
                         int p_begin, int P, int na_shift, int bin_stride)
{
    int p = p_begin + blockIdx.x * blockDim.x + threadIdx.x;
    if (p < P) {
        int i0 = idx0[p], i1 = idx1[p];
        float t = dist[p] * K1_F;
        float u = fmaf(-t, t, 1.0f);
        if (u > 0.0f) {
            unsigned int w0 = g_packed[i0 >> 4];
            unsigned int w1 = g_packed[i1 >> 4];
            int s0 = (int)((w0 >> ((i0 & 15) << 1)) & 3u);
            int s1 = (int)((w1 >> ((i1 & 15) << 1)) & 3u);
            float2 c = g_tab[(s0 << 2) + s1];
            float r = rcp_approx(u);
            float arg = fmaf(c.y, dist[p], fmaf(-L2E_F, r, L2E_F));
            float srb = c.x * ex2_approx(arg);
            int mol = i0 >> na_shift;
            atomicAdd(&g_bins[mol * bin_stride], srb);
        }
    }
}

// ---------------------------------------------------------------------------
// Generic fallback (any n_elem / non-pow2 n_atoms / large n_sp)
// ---------------------------------------------------------------------------
__global__ void __launch_bounds__(256)
srb_kernel_generic(const int* __restrict__ idx0, const int* __restrict__ idx1,
                   const float* __restrict__ dist, const int* __restrict__ species,
                   const float* __restrict__ pre_tab, const float* __restrict__ dfac_tab,
                   int P, int n_elem, int na_shift, int n_atoms, int bin_stride)
{
    __shared__ float2 s_tab[64];
    int ne2 = n_elem * n_elem;
    for (int j = threadIdx.x; j < ne2; j += blockDim.x)
        s_tab[j] = make_float2(pre_tab[j], dfac_tab[j] * A2B_F * L2E_F);
    __syncthreads();

    int tid = blockIdx.x * blockDim.x + threadIdx.x;
    int stride = gridDim.x * blockDim.x;
    for (int p = tid; p < P; p += stride) {
        int i0 = idx0[p], i1 = idx1[p];
        float t = dist[p] * K1_F;
        float u = fmaf(-t, t, 1.0f);
        if (u > 0.0f) {
            int s0 = species[i0];
            int s1 = species[i1];
            float2 c = s_tab[s0 * n_elem + s1];
            float r = rcp_approx(u);
            float arg = fmaf(c.y, dist[p], fmaf(-L2E_F, r, L2E_F));
            float srb = c.x * ex2_approx(arg);
            int mol = (na_shift >= 0) ? (i0 >> na_shift) : (i0 / n_atoms);
            atomicAdd(&g_bins[mol * bin_stride], srb);
        }
    }
}

// ---------------------------------------------------------------------------
// Finalize. cast_done=1: species cast already written by init; only energies.
// ---------------------------------------------------------------------------
__global__ void finalize_kernel(const float* __restrict__ energies,
                                const int* __restrict__ species,
                                float* __restrict__ out,
                                int n_mol, int n_sp, int bin_stride,
                                int mode, int cast_done) {
    int t = blockIdx.x * blockDim.x + threadIdx.x;
    if (cast_done) {
        if (mode != 2) {
            int base = (mode == 1) ? n_sp : 0;
            if (t < n_mol)
                out[base + t] = energies[t] + g_bins[t * bin_stride];
        }
        return;
    }
    if (mode == 1) {
        int n4 = n_sp >> 2;
        if (t < n4) {
            int4 s = ((const int4*)species)[t];
            ((float4*)out)[t] = make_float4((float)s.x, (float)s.y,
                                            (float)s.z, (float)s.w);
        } else if (t < n4 + n_mol) {
            int m = t - n4;
            out[n_sp + m] = energies[m] + g_bins[m * bin_stride];
        }
        int rem = n_sp & 3;
        if (t < rem) {
            int a = (n_sp & ~3) + t;
            out[a] = (float)species[a];
        }
    } else if (mode == 2) {
        if (t < n_sp) out[t] = (float)species[t];
    } else {
        if (t < n_mol) out[t] = energies[t] + g_bins[t * bin_stride];
    }
}

// ---------------------------------------------------------------------------
extern "C" void kernel_launch(void* const* d_in, const int* in_sizes, int n_in,
                              void* d_out, int out_size) {
    const int*   species  = (const int*)d_in[0];
    const float* energies = (const float*)d_in[1];
    const int*   ai12     = (const int*)d_in[2];
    const float* dist     = (const float*)d_in[3];
    const float* pre_tab  = (const float*)d_in[4];
    const float* dfac_tab = (const float*)d_in[5];

    int n_sp  = in_sizes[0];
    int n_mol = in_sizes[1];
    int P     = in_sizes[3];
    int n_atoms = (n_mol > 0) ? (n_sp / n_mol) : 1;
    if (n_atoms < 1) n_atoms = 1;

    int n_elem = 1;
    while (n_elem * n_elem < in_sizes[4]) n_elem++;

    int na_shift = -1;
    if ((n_atoms & (n_atoms - 1)) == 0) {
        int s = 0; int v = n_atoms;
        while (v > 1) { v >>= 1; s++; }
        na_shift = s;
    }

    bool packed = (n_elem == 4) && (n_sp <= MAX_ATOKENS) && (na_shift >= 0);
    int bin_stride = (n_mol <= MAX_MOLS) ? BIN_STRIDE : 1;

    int nwords = (n_sp + 15) >> 4;
    int nwords_pad = (nwords + 3) & ~3;
    int n_mol_pad = (n_mol + 3) & ~3;

    float* out = (float*)d_out;
    int mode;
    if (out_size == n_mol) mode = 0;
    else if (out_size == n_sp + n_mol) mode = 1;
    else if (out_size == n_sp) mode = 2;
    else mode = 0;

    int do_cast = (packed && (mode == 1 || mode == 2)) ? 1 : 0;

    long long init_n = n_mol;
    if (packed) {
        long long pack_n = (long long)(n_sp >> 2) + 1;
        if (pack_n > init_n) init_n = pack_n;
    }
    if (init_n < 16) init_n = 16;
    int init_grid = (int)((init_n + 255) / 256);
    init_kernel<<<init_grid, 256>>>(species, pre_tab, dfac_tab, out,
                                    n_sp, n_mol, n_elem * n_elem,
                                    bin_stride, packed ? 1 : 0, do_cast);

    const int* idx0 = ai12;
    const int* idx1 = ai12 + P;

    size_t smem_sbin = (size_t)(TAB_WORDS + n_mol_pad + nwords_pad) * 4;
    bool sbin_fits = packed && (n_mol <= MAX_MOLS) && (2 * smem_sbin <= 220 * 1024);

    if (sbin_fits) {
        (void)cudaFuncSetAttribute(srb_main_sbin,
                                   cudaFuncAttributeMaxDynamicSharedMemorySize,
                                   (int)smem_sbin);
        int nv = P >> 2;
        int grid = 148 * 2;              // proven config
        long long want = ((long long)nv + BLOCK - 1) / BLOCK;
        if (want < grid) grid = (int)(want > 0 ? want : 1);
        if (grid < 1) grid = 1;
        srb_main_sbin<<<grid, BLOCK, smem_sbin>>>(idx0, idx1, dist,
                                                  nv, na_shift, bin_stride,
                                                  nwords_pad, n_mol, n_mol_pad);
        int rem = P & 3;
        if (rem)
            srb_tail<<<1, 32>>>(idx0, idx1, dist, P - rem, P, na_shift, bin_stride);

        long long fin_threads = do_cast ? n_mol
                              : ((mode == 1) ? ((long long)(n_sp >> 2) + n_mol + 4)
                              : ((mode == 2) ? n_sp : n_mol));
        int fin_grid = (int)((fin_threads + 255) / 256);
        if (fin_grid < 1) fin_grid = 1;
        finalize_kernel<<<fin_grid, 256>>>(energies, species, out,
                                           n_mol, n_sp, bin_stride, mode, do_cast);
    } else {
        long long want = ((long long)P + 255) / 256;
        int grid = (want > 4736) ? 4736 : (int)(want > 0 ? want : 1);
        srb_kernel_generic<<<grid, 256>>>(idx0, idx1, dist, species,
                                          pre_tab, dfac_tab,
                                          P, n_elem, na_shift, n_atoms, bin_stride);
        long long fin_threads = (mode == 1) ? ((long long)(n_sp >> 2) + n_mol + 4)
                              : ((mode == 2) ? n_sp : n_mol);
        int fin_grid = (int)((fin_threads + 255) / 256);
        if (fin_grid < 1) fin_grid = 1;
        finalize_kernel<<<fin_grid, 256>>>(energies, species, out,
                                           n_mol, n_sp, bin_stride, mode, 0);
    }
}

// round 13
// speedup vs baseline: 1.3735x; 1.1404x over previous
#include <cuda_runtime.h>

// ---------------------------------------------------------------------------
// EnergySRB R13 = R12 minus the finalize launch:
//  - init pre-loads out[base..base+n_mol) with energies; main CTAs flush their
//    smem bins straight into out via coalesced atomicAdd. g_bins/finalize gone
//    on the fast path (2 launches total). Flush volume unchanged (~1.2M
//    coalesced REDGs, ~3us overlapped tail).
//  - hot loop / grid 296 / CULL -17 / packed species / replicated table:
//    all frozen from R12 (49.9us).
// ---------------------------------------------------------------------------

#define A2B_F 1.8897261258369282f
#define RC_F 9.826575854352027f          // 5.2 * A2B (bohr)
#define K1_F (A2B_F / RC_F)              // dv*K1 = d/rc
#define L2E_F 1.4426950408889634f
#define CULL_F (-17.0f)
#define DVCLAMP_F 5.19f                  // < 5.2 angstrom: guarantees u > 0

#define MAX_ATOKENS (512 * 1024)
#define MAX_MOLS (8192)
#define BIN_STRIDE 132                    // used by generic fallback only
#define BLOCK 1024
#define TAB_WORDS 272                     // 8 replicas * 17 float2 = 1088B

__device__ unsigned int g_packed[MAX_ATOKENS / 16];   // 2-bit species codes
__device__ float g_bins[MAX_MOLS * BIN_STRIDE];       // fallback path scratch
__device__ float2 g_tab[16];                          // (pre, dfac*A2B*L2E)
__device__ float g_dvcut;

__device__ __forceinline__ float rcp_approx(float x) {
    float y; asm("rcp.approx.f32 %0, %1;" : "=f"(y) : "f"(x)); return y;
}
__device__ __forceinline__ float ex2_approx(float x) {
    float y; asm("ex2.approx.f32 %0, %1;" : "=f"(y) : "f"(x)); return y;
}

// ---------------------------------------------------------------------------
// Init: pack species (shuffle combine), cast species into out (same int4
// load), table + dvcut via warp reduce, pre-load out energies (fast path)
// or zero g_bins (fallback path).
// ---------------------------------------------------------------------------
__global__ void init_kernel(const int* __restrict__ species,
                            const float* __restrict__ pre_tab,
                            const float* __restrict__ dfac_tab,
                            const float* __restrict__ energies,
                            float* __restrict__ out,
                            int n_sp, int n_mol, int ne2,
                            int do_pack, int do_cast,
                            int e_base, int direct_out) {
    int t = blockIdx.x * blockDim.x + threadIdx.x;
    if (do_pack) {
        int n4 = n_sp >> 2;
        int n4f = (n_sp >> 4) << 2;       // int4 groups forming full 16-atom words
        if (t < n4) {
            int4 v = ((const int4*)species)[t];
            if (do_cast) {
                ((float4*)out)[t] = make_float4((float)v.x, (float)v.y,
                                                (float)v.z, (float)v.w);
            }
            if (t < n4f) {
                unsigned int chunk =
                    ((unsigned)v.x & 3u)        | (((unsigned)v.y & 3u) << 2) |
                    (((unsigned)v.z & 3u) << 4) | (((unsigned)v.w & 3u) << 6);
                unsigned int sub = (unsigned)t & 3u;
                unsigned int w = chunk << (sub * 8u);
                unsigned int gbase = (unsigned)(threadIdx.x & 31) & ~3u;
                unsigned int mask = 0xFu << gbase;
                w |= __shfl_xor_sync(mask, w, 1);
                w |= __shfl_xor_sync(mask, w, 2);
                if (sub == 0) g_packed[t >> 2] = w;
            }
        }
        if (t == n4 && (n_sp & 15)) {     // partial last packed word
            int wi = n_sp >> 4;
            unsigned int w = 0;
            int base = wi << 4;
            for (int j = 0; j < 16; j++) {
                int a = base + j;
                unsigned int v = (a < n_sp) ? ((unsigned int)species[a] & 3u) : 0u;
                w |= v << (2 * j);
            }
            g_packed[wi] = w;
        }
        if (do_cast && t < (n_sp & 3)) {  // cast remainder
            int a = (n_sp & ~3) + t;
            out[a] = (float)species[a];
        }
        // table + dvcut: lanes 0-15 of block 0, parallel loads + shfl reduce
        if (blockIdx.x == 0 && threadIdx.x < 16) {
            int lane = threadIdx.x;
            float c = -1e30f;
            if (lane < ne2) {
                float d = dfac_tab[lane] * A2B_F * L2E_F;
                g_tab[lane] = make_float2(pre_tab[lane], d);
                c = d;
            }
            #pragma unroll
            for (int off = 8; off; off >>= 1)
                c = fmaxf(c, __shfl_xor_sync(0xFFFFu, c, off));
            if (lane == 0) {
                float cut = (c < 0.0f) ? (CULL_F / c) : 1e30f;
                if (cut > DVCLAMP_F) cut = DVCLAMP_F;   // survivors => u > 0
                g_dvcut = cut;
            }
        }
    }
    if (t < n_mol) {
        if (direct_out) out[e_base + t] = energies[t];   // fast path
        else            g_bins[t * BIN_STRIDE] = 0.0f;   // fallback scratch
    }
}

// ---------------------------------------------------------------------------
// Main kernel: smem bins, flush straight into out[e_base..].
// smem: coef table replicas | bins | packed species.
// ---------------------------------------------------------------------------
__global__ void __launch_bounds__(BLOCK, 2)
srb_main_out(const int* __restrict__ idx0, const int* __restrict__ idx1,
             const float* __restrict__ dist, float* __restrict__ out,
             int nv, int na_shift, int nwords,
             int n_mol, int n_mol_pad, int e_base)
{
    extern __shared__ unsigned int s_mem[];
    float2* s_tab = (float2*)s_mem;                // 8 replicas, stride 17
    float* s_bins = (float*)(s_mem + TAB_WORDS);
    unsigned int* s_pk = s_mem + TAB_WORDS + n_mol_pad;

    if (threadIdx.x < 128) {
        int rep = threadIdx.x >> 4;
        int e = threadIdx.x & 15;
        s_tab[rep * 17 + e] = g_tab[e];
    }
    for (int j = threadIdx.x; j < n_mol; j += BLOCK)
        s_bins[j] = 0.0f;
    {
        const int4* __restrict__ src = (const int4*)g_packed;
        int4* dst = (int4*)s_pk;
        int nv4 = nwords >> 2;
        for (int j = threadIdx.x; j < nv4; j += BLOCK)
            dst[j] = src[j];
    }
    float dvcut = g_dvcut;
    int rbase = (threadIdx.x & 7) * 17;            // per-lane table replica
    __syncthreads();

    int tid = blockIdx.x * BLOCK + threadIdx.x;
    int stride = gridDim.x * BLOCK;

    const int4* __restrict__ p0 = (const int4*)idx0;
    const int4* __restrict__ p1 = (const int4*)idx1;
    const float4* __restrict__ pd = (const float4*)dist;

    for (int i = tid; i < nv; i += stride) {
        int4 a = __ldcs(p0 + i);
        int4 b = __ldcs(p1 + i);
        float4 dd = __ldcs(pd + i);

        int ia[4] = {a.x, a.y, a.z, a.w};
        int ib[4] = {b.x, b.y, b.z, b.w};
        float dv[4] = {dd.x, dd.y, dd.z, dd.w};

        #pragma unroll
        for (int j = 0; j < 4; j++) {
            float dvj = dv[j];
            if (dvj < dvcut) {                     // safe cull; implies u > 0
                int i0 = ia[j], i1 = ib[j];
                unsigned int w0 = s_pk[i0 >> 4];
                unsigned int w1 = s_pk[i1 >> 4];
                int s0 = (int)((w0 >> ((i0 & 15) << 1)) & 3u);
                int s1 = (int)((w1 >> ((i1 & 15) << 1)) & 3u);
                float2 c = s_tab[rbase + ((s0 << 2) | s1)];

                float t = dvj * K1_F;
                float u = fmaf(-t, t, 1.0f);       // 1 - (d/rc)^2, > 0 here
                float r = rcp_approx(u);
                float arg = fmaf(c.y, dvj, fmaf(-L2E_F, r, L2E_F));

                if (arg > CULL_F) {
                    float srb = c.x * ex2_approx(arg);
                    int mol = i0 >> na_shift;
                    atomicAdd(&s_bins[mol], srb);  // smem RED (spread banks)
                }
            }
        }
    }

    // flush per-CTA bins straight into the output (coalesced REDG burst)
    __syncthreads();
    for (int j = threadIdx.x; j < n_mol; j += BLOCK) {
        float v = s_bins[j];
        if (v != 0.0f)
            atomicAdd(&out[e_base + j], v);
    }
}

// tail pairs [p_begin, P) scalar (exact, no cull) -> direct to out
__global__ void srb_tail(const int* __restrict__ idx0, const int* __restrict__ idx1,
                         const float* __restrict__ dist, float* __restrict__ out,
                         int p_begin, int P, int na_shift, int e_base)
{
    int p = p_begin + blockIdx.x * blockDim.x + threadIdx.x;
    if (p < P) {
        int i0 = idx0[p], i1 = idx1[p];
        float t = dist[p] * K1_F;
        float u = fmaf(-t, t, 1.0f);
        if (u > 0.0f) {
            unsigned int w0 = g_packed[i0 >> 4];
            unsigned int w1 = g_packed[i1 >> 4];
            int s0 = (int)((w0 >> ((i0 & 15) << 1)) & 3u);
            int s1 = (int)((w1 >> ((i1 & 15) << 1)) & 3u);
            float2 c = g_tab[(s0 << 2) + s1];
            float r = rcp_approx(u);
            float arg = fmaf(c.y, dist[p], fmaf(-L2E_F, r, L2E_F));
            float srb = c.x * ex2_approx(arg);
            int mol = i0 >> na_shift;
            atomicAdd(&out[e_base + mol], srb);
        }
    }
}

// ---------------------------------------------------------------------------
// Generic fallback (any n_elem / non-pow2 n_atoms / large n_sp) -> g_bins
// ---------------------------------------------------------------------------
__global__ void __launch_bounds__(256)
srb_kernel_generic(const int* __restrict__ idx0, const int* __restrict__ idx1,
                   const float* __restrict__ dist, const int* __restrict__ species,
                   const float* __restrict__ pre_tab, const float* __restrict__ dfac_tab,
                   int P, int n_elem, int na_shift, int n_atoms)
{
    __shared__ float2 s_tab[64];
    int ne2 = n_elem * n_elem;
    for (int j = threadIdx.x; j < ne2; j += blockDim.x)
        s_tab[j] = make_float2(pre_tab[j], dfac_tab[j] * A2B_F * L2E_F);
    __syncthreads();

    int tid = blockIdx.x * blockDim.x + threadIdx.x;
    int stride = gridDim.x * blockDim.x;
    for (int p = tid; p < P; p += stride) {
        int i0 = idx0[p], i1 = idx1[p];
        float t = dist[p] * K1_F;
        float u = fmaf(-t, t, 1.0f);
        if (u > 0.0f) {
            int s0 = species[i0];
            int s1 = species[i1];
            float2 c = s_tab[s0 * n_elem + s1];
            float r = rcp_approx(u);
            float arg = fmaf(c.y, dist[p], fmaf(-L2E_F, r, L2E_F));
            float srb = c.x * ex2_approx(arg);
            int mol = (na_shift >= 0) ? (i0 >> na_shift) : (i0 / n_atoms);
            atomicAdd(&g_bins[mol * BIN_STRIDE], srb);
        }
    }
}

// fallback finalize (generic path only)
__global__ void finalize_kernel(const float* __restrict__ energies,
                                const int* __restrict__ species,
                                float* __restrict__ out,
                                int n_mol, int n_sp, int mode) {
    int t = blockIdx.x * blockDim.x + threadIdx.x;
    if (mode == 1) {
        int n4 = n_sp >> 2;
        if (t < n4) {
            int4 s = ((const int4*)species)[t];
            ((float4*)out)[t] = make_float4((float)s.x, (float)s.y,
                                            (float)s.z, (float)s.w);
        } else if (t < n4 + n_mol) {
            int m = t - n4;
            out[n_sp + m] = energies[m] + g_bins[m * BIN_STRIDE];
        }
        int rem = n_sp & 3;
        if (t < rem) {
            int a = (n_sp & ~3) + t;
            out[a] = (float)species[a];
        }
    } else if (mode == 2) {
        if (t < n_sp) out[t] = (float)species[t];
    } else {
        if (t < n_mol) out[t] = energies[t] + g_bins[t * BIN_STRIDE];
    }
}

// ---------------------------------------------------------------------------
extern "C" void kernel_launch(void* const* d_in, const int* in_sizes, int n_in,
                              void* d_out, int out_size) {
    const int*   species  = (const int*)d_in[0];
    const float* energies = (const float*)d_in[1];
    const int*   ai12     = (const int*)d_in[2];
    const float* dist     = (const float*)d_in[3];
    const float* pre_tab  = (const float*)d_in[4];
    const float* dfac_tab = (const float*)d_in[5];

    int n_sp  = in_sizes[0];
    int n_mol = in_sizes[1];
    int P     = in_sizes[3];
    int n_atoms = (n_mol > 0) ? (n_sp / n_mol) : 1;
    if (n_atoms < 1) n_atoms = 1;

    int n_elem = 1;
    while (n_elem * n_elem < in_sizes[4]) n_elem++;

    int na_shift = -1;
    if ((n_atoms & (n_atoms - 1)) == 0) {
        int s = 0; int v = n_atoms;
        while (v > 1) { v >>= 1; s++; }
        na_shift = s;
    }

    bool packed = (n_elem == 4) && (n_sp <= MAX_ATOKENS) && (na_shift >= 0);

    int nwords = (n_sp + 15) >> 4;
    int nwords_pad = (nwords + 3) & ~3;
    int n_mol_pad = (n_mol + 3) & ~3;

    float* out = (float*)d_out;
    int mode;
    if (out_size == n_mol) mode = 0;
    else if (out_size == n_sp + n_mol) mode = 1;
    else if (out_size == n_sp) mode = 2;
    else mode = 0;

    size_t smem_sbin = (size_t)(TAB_WORDS + n_mol_pad + nwords_pad) * 4;
    bool fast = packed && (n_mol <= MAX_MOLS) && (2 * smem_sbin <= 220 * 1024);

    int do_cast = (packed && (mode == 1 || mode == 2)) ? 1 : 0;
    int e_base = (mode == 1) ? n_sp : 0;
    int direct_out = (fast && mode != 2) ? 1 : 0;

    long long init_n = n_mol;
    if (packed) {
        long long pack_n = (long long)(n_sp >> 2) + 1;
        if (pack_n > init_n) init_n = pack_n;
    }
    if (init_n < 16) init_n = 16;
    int init_grid = (int)((init_n + 255) / 256);
    init_kernel<<<init_grid, 256>>>(species, pre_tab, dfac_tab, energies, out,
                                    n_sp, n_mol, n_elem * n_elem,
                                    packed ? 1 : 0, do_cast, e_base,
                                    fast ? 1 : 0);

    const int* idx0 = ai12;
    const int* idx1 = ai12 + P;

    if (fast) {
        if (mode != 2) {
            (void)cudaFuncSetAttribute(srb_main_out,
                                       cudaFuncAttributeMaxDynamicSharedMemorySize,
                                       (int)smem_sbin);
            int nv = P >> 2;
            int grid = 148 * 2;              // proven config
            long long want = ((long long)nv + BLOCK - 1) / BLOCK;
            if (want < grid) grid = (int)(want > 0 ? want : 1);
            if (grid < 1) grid = 1;
            srb_main_out<<<grid, BLOCK, smem_sbin>>>(idx0, idx1, dist, out,
                                                     nv, na_shift, nwords_pad,
                                                     n_mol, n_mol_pad, e_base);
            int rem = P & 3;
            if (rem)
                srb_tail<<<1, 32>>>(idx0, idx1, dist, out,
                                    P - rem, P, na_shift, e_base);
        }
        // mode==2: species cast written by init; no energy output region.
    } else {
        long long want = ((long long)P + 255) / 256;
        int grid = (want > 4736) ? 4736 : (int)(want > 0 ? want : 1);
        srb_kernel_generic<<<grid, 256>>>(idx0, idx1, dist, species,
                                          pre_tab, dfac_tab,
                                          P, n_elem, na_shift, n_atoms);
        long long fin_threads = (mode == 1) ? ((long long)(n_sp >> 2) + n_mol + 4)
                              : ((mode == 2) ? n_sp : n_mol);
        int fin_grid = (int)((fin_threads + 255) / 256);
        if (fin_grid < 1) fin_grid = 1;
        finalize_kernel<<<fin_grid, 256>>>(energies, species, out,
                                           n_mol, n_sp, mode);
    }
}